// round 5
// baseline (speedup 1.0000x reference)
#include <cuda_runtime.h>
#include <cstdint>
#include <math.h>

#define Bq 128
#define Tq 512
#define Cq 100
#define Eq 64
#define Hq 256
#define G7 1792   // 7*H
#define KIN 320   // E+H

typedef unsigned long long ull;

// ---- scratch (device globals; no allocation in kernel_launch) ----
static __device__ float g_r[(size_t)Bq * Tq * Eq];          // rec_input
static __device__ float g_gin[(size_t)Bq * Tq * G7];        // input-side gates (+bias)

__device__ __forceinline__ float sigmf_(float x) { return 1.f / (1.f + expf(-x)); }
__device__ __forceinline__ float softplusf_(float x) {
    return fmaxf(x, 0.f) + log1pf(expf(-fabsf(x)));
}
// fast variants (abs err ~1e-6, budget 1e-3)
__device__ __forceinline__ float sigf(float x) {
    return __fdividef(1.f, 1.f + __expf(-x));
}
__device__ __forceinline__ float tanf_(float x) {
    return 1.f - 2.f * __fdividef(1.f, 1.f + __expf(2.f * x));
}
__device__ __forceinline__ float splusf(float x) {
    return fmaxf(x, 0.f) + __logf(1.f + __expf(-fabsf(x)));
}
__device__ __forceinline__ void fma2_(ull& d, ull a, ull b) {
    asm volatile("fma.rn.f32x2 %0, %1, %2, %0;" : "+l"(d) : "l"(a), "l"(b));
}
__device__ __forceinline__ ull dup2_(float x) {
    ull d;
    asm("mov.b64 %0, {%1, %1};" : "=l"(d) : "f"(x));
    return d;
}
__device__ __forceinline__ float lo_(ull v) { return __uint_as_float((unsigned)v); }
__device__ __forceinline__ float hi_(ull v) { return __uint_as_float((unsigned)(v >> 32)); }

// ---------------------------------------------------------------------------
// K1: rec_input
// ---------------------------------------------------------------------------
__global__ __launch_bounds__(128) void k_embed(const float* __restrict__ marks,
                                               const float* __restrict__ Wemb) {
    int bt = blockIdx.x;
    __shared__ float sm[Cq];
    int tid = threadIdx.x;
    if (tid < Cq) sm[tid] = marks[(size_t)bt * Cq + tid];
    __syncthreads();
    if (tid < Eq) {
        float cnt = 0.f, s = 0.f;
        #pragma unroll
        for (int c = 0; c < Cq; c++) {
            float m = sm[c];
            cnt += m;
            s = fmaf(m, Wemb[c * Eq + tid], s);
        }
        g_r[(size_t)bt * Eq + tid] = s / fmaxf(cnt, 1.f);
    }
}

// ---------------------------------------------------------------------------
// K2: g_gin[bt, j] = g_r[bt,:] @ W_cell[j, 0:64]^T + b_cell[j]   (f32x2)
// ---------------------------------------------------------------------------
__global__ __launch_bounds__(256) void k_gin(const float* __restrict__ Wc,
                                             const float* __restrict__ bc) {
    __shared__ float As[64 * 68];
    __shared__ float Bs[64 * 132];
    int tid = threadIdx.x;
    int row0 = blockIdx.x * 64, col0 = blockIdx.y * 128;

    #pragma unroll
    for (int i = 0; i < 16; i++) {
        int idx = i * 256 + tid;
        int row = idx >> 6, k = idx & 63;
        As[k * 68 + row] = g_r[(size_t)(row0 + row) * Eq + k];
    }
    #pragma unroll
    for (int i = 0; i < 32; i++) {
        int idx = i * 256 + tid;
        int col = idx >> 6, k = idx & 63;
        Bs[k * 132 + col] = Wc[(size_t)(col0 + col) * KIN + k];
    }
    __syncthreads();

    int tx = tid & 15, ty = tid >> 4;
    ull acc2[4][4];
    #pragma unroll
    for (int i = 0; i < 4; i++)
        #pragma unroll
        for (int p = 0; p < 4; p++) acc2[i][p] = 0ull;

    #pragma unroll 4
    for (int k = 0; k < 64; k++) {
        float4 a = *(const float4*)&As[k * 68 + ty * 4];
        ulonglong2 b01 = *(const ulonglong2*)&Bs[k * 132 + tx * 8];
        ulonglong2 b23 = *(const ulonglong2*)&Bs[k * 132 + tx * 8 + 4];
        ull ad[4] = {dup2_(a.x), dup2_(a.y), dup2_(a.z), dup2_(a.w)};
        #pragma unroll
        for (int i = 0; i < 4; i++) {
            fma2_(acc2[i][0], ad[i], b01.x);
            fma2_(acc2[i][1], ad[i], b01.y);
            fma2_(acc2[i][2], ad[i], b23.x);
            fma2_(acc2[i][3], ad[i], b23.y);
        }
    }

    float bb[8];
    #pragma unroll
    for (int jx = 0; jx < 8; jx++) bb[jx] = bc[col0 + tx * 8 + jx];

    #pragma unroll
    for (int i = 0; i < 4; i++) {
        size_t base = (size_t)(row0 + ty * 4 + i) * G7 + col0 + tx * 8;
        float4 o0 = {lo_(acc2[i][0]) + bb[0], hi_(acc2[i][0]) + bb[1],
                     lo_(acc2[i][1]) + bb[2], hi_(acc2[i][1]) + bb[3]};
        float4 o1 = {lo_(acc2[i][2]) + bb[4], hi_(acc2[i][2]) + bb[5],
                     lo_(acc2[i][3]) + bb[6], hi_(acc2[i][3]) + bb[7]};
        *(float4*)&g_gin[base]     = o0;
        *(float4*)&g_gin[base + 4] = o1;
    }
}

// ---------------------------------------------------------------------------
// K3: initial state -> out[b,0,:]
// ---------------------------------------------------------------------------
__global__ __launch_bounds__(256) void k_init(const float* __restrict__ init,
                                              float* __restrict__ out) {
    int b = blockIdx.x, k = threadIdx.x;
    float s0 = init[k], s1 = init[Hq + k], s2 = init[2 * Hq + k];
    float s3 = init[3 * Hq + k], s4 = init[4 * Hq + k], s5 = init[5 * Hq + k];
    float hd0 = tanhf(s0), cd0 = tanhf(s1), cb0 = tanhf(s2), c0 = tanhf(s3);
    float d0 = softplusf_(s4), o0 = sigmf_(s5);
    size_t base = (size_t)b * (Tq + 1) * (6 * Hq);
    out[base + 0 * Hq + k] = hd0;
    out[base + 1 * Hq + k] = o0;
    out[base + 2 * Hq + k] = cb0;
    out[base + 3 * Hq + k] = c0;
    out[base + 4 * Hq + k] = d0;
    out[base + 5 * Hq + k] = cd0;
}

// ---------------------------------------------------------------------------
// K4: recurrence. grid = 128 = 8 clusters of 16 CTAs. Cluster = batch-group
//   of 16 b; cluster-rank = j-slice of 16 j. 512 threads, 16 warps =
//   kw(4 k-split) x jh(4 j-quarter); lane = jq(4 j) x bl(8 b-pairs); thread
//   tile 7g x 2b x 1j x 64k in fma.rn.f32x2. Phase 2 (threads 0..255): reduce
//   4 k-partials, nonlinearities, decay, write out; then PUSH h into all 16
//   peers' SMEM (st.shared::cluster, double-buffered) + one cluster barrier.
// ---------------------------------------------------------------------------
__global__ void __cluster_dims__(16, 1, 1) __launch_bounds__(512, 1)
k_recur(const float* __restrict__ Wc, const float* __restrict__ ts,
        const float* __restrict__ init, float* __restrict__ out) {
    extern __shared__ float sh[];
    float* Ws  = sh;            // 28672 floats: [(g*64+kq)*16 + j][k&3]
    float* hsb = sh + 28672;    // 2 x 4096 floats: swizzled h [buf][b][k]
    float* red = sh + 36864;    // 8064 floats: [(kw*7+g)*16 + j][18 b-pad]

    int tid = threadIdx.x;
    int group = blockIdx.x >> 4;     // cluster id 0..7
    int rank  = blockIdx.x & 15;     // cluster rank 0..15
    int j0 = rank * 16;

    // phase-1 identity
    int w = tid >> 5, lane = tid & 31;
    int kw = w & 3, jh = w >> 2;
    int jq = lane >> 3, bl = lane & 7;
    int j1 = jh * 4 + jq;

    // phase-2 identity (threads 0..255)
    int j2 = tid & 15, b2 = (tid >> 4) & 15;
    int jg2 = j0 + j2;
    int bg2 = group * 16 + b2;
    bool p2 = tid < 256;

    // one-time weight load: LDG coalesced along k
    for (int idx = tid; idx < 7 * 16 * 256; idx += 512) {
        int g = idx >> 12, jw = (idx >> 8) & 15, k = idx & 255;
        int row = g * Hq + j0 + jw;
        Ws[((g * 64 + (k >> 2)) * 16 + jw) * 4 + (k & 3)] =
            Wc[(size_t)row * KIN + Eq + k];
    }

    // initial h fill (identical for all batches): hs[0][b][k] = tanh(init[k])
    for (int idx = tid; idx < 4096; idx += 512) {
        int b = idx >> 8, k = idx & 255;
        int f4 = b * 64 + ((k >> 2) ^ ((b >> 1) & 7) ^ ((b & 1) << 3));
        hsb[f4 * 4 + (k & 3)] = tanhf(init[k]);
    }

    float c_st = 0.f, cb_st = 0.f;
    int fidx2 = 0;
    if (p2) {
        c_st  = tanhf(init[3 * Hq + jg2]);
        cb_st = tanhf(init[2 * Hq + jg2]);
        int f4 = b2 * 64 + ((jg2 >> 2) ^ ((b2 >> 1) & 7) ^ ((b2 & 1) << 3));
        fidx2 = f4 * 4 + (jg2 & 3);
    }
    __syncthreads();

    for (int t = 0; t < Tq; t++) {
        const float* hcur = hsb + (t & 1) * 4096;
        float* hnxt       = hsb + ((t & 1) ^ 1) * 4096;

        // ---- prefetch input-side gates + timestamps (phase-2 identity) ----
        float ain[7], tc = 0.f, tp = 0.f;
        if (p2) {
            size_t gbase = ((size_t)bg2 * Tq + t) * (size_t)G7 + jg2;
            #pragma unroll
            for (int g = 0; g < 7; g++) ain[g] = __ldcs(&g_gin[gbase + g * Hq]);
            tc = ts[bg2 * Tq + t];
            tp = (t > 0) ? ts[bg2 * Tq + t - 1] : 0.f;
        }

        // ---- phase 1: packed-f32x2 GEMM over k-range [kw*64, kw*64+64) ----
        ull acc[7][2];
        #pragma unroll
        for (int g = 0; g < 7; g++) { acc[g][0] = 0ull; acc[g][1] = 0ull; }

        const ulonglong2* hsu = (const ulonglong2*)hcur;
        int b0 = 2 * bl, b1 = 2 * bl + 1;
        #pragma unroll 4
        for (int q = 0; q < 16; q++) {
            int q4 = kw * 16 + q;
            ulonglong2 h0 = hsu[b0 * 64 + (q4 ^ bl)];
            ulonglong2 h1 = hsu[b1 * 64 + (q4 ^ bl ^ 8)];
            #pragma unroll
            for (int g = 0; g < 7; g++) {
                ulonglong2 wv = *(const ulonglong2*)&Ws[((g * 64 + q4) * 16 + j1) * 4];
                fma2_(acc[g][0], wv.x, h0.x);
                fma2_(acc[g][0], wv.y, h0.y);
                fma2_(acc[g][1], wv.x, h1.x);
                fma2_(acc[g][1], wv.y, h1.y);
            }
        }

        // ---- store k-partials ----
        #pragma unroll
        for (int g = 0; g < 7; g++) {
            float2 v;
            v.x = lo_(acc[g][0]) + hi_(acc[g][0]);
            v.y = lo_(acc[g][1]) + hi_(acc[g][1]);
            *(float2*)&red[((kw * 7 + g) * 16 + j1) * 18 + 2 * bl] = v;
        }
        __syncthreads();

        // ---- phase 2: reduce + nonlinearities + decay + writes + h push ----
        if (p2) {
            float gate[7];
            #pragma unroll
            for (int g = 0; g < 7; g++) {
                float s = red[((0 * 7 + g) * 16 + j2) * 18 + b2]
                        + red[((1 * 7 + g) * 16 + j2) * 18 + b2]
                        + red[((2 * 7 + g) * 16 + j2) * 18 + b2]
                        + red[((3 * 7 + g) * 16 + j2) * 18 + b2];
                gate[g] = s + ain[g];
            }

            float gi  = sigf(gate[0]);
            float gf  = sigf(gate[1]);
            float gz  = tanf_(gate[2]);
            float go  = sigf(gate[3]);
            float gib = sigf(gate[4]);
            float gfb = sigf(gate[5]);
            float gd  = splusf(gate[6]);
            float dt  = tc - tp;

            float ct  = gf * c_st + gi * gz;
            float cbt = gfb * cb_st + gib * gz;
            float cdt = cbt + (ct - cbt) * __expf(-gd * dt);
            float hdt = go * tanf_(cdt);

            size_t ob = ((size_t)bg2 * (Tq + 1) + t + 1) * (size_t)(6 * Hq) + jg2;
            __stcs(&out[ob + 0 * Hq], hdt);
            __stcs(&out[ob + 1 * Hq], go);
            __stcs(&out[ob + 2 * Hq], cbt);
            __stcs(&out[ob + 3 * Hq], ct);
            __stcs(&out[ob + 4 * Hq], gd);
            __stcs(&out[ob + 5 * Hq], cdt);

            c_st = ct; cb_st = cbt;

            // push h into all 16 cluster CTAs' SMEM (incl. self)
            uint32_t la = (uint32_t)__cvta_generic_to_shared(hnxt + fidx2);
            #pragma unroll
            for (int r = 0; r < 16; r++) {
                uint32_t ra;
                asm volatile("mapa.shared::cluster.u32 %0, %1, %2;"
                             : "=r"(ra) : "r"(la), "r"(r));
                asm volatile("st.shared::cluster.f32 [%0], %1;"
                             :: "r"(ra), "f"(hdt) : "memory");
            }
        }

        // ---- cluster barrier: release pushes / acquire peers' pushes ----
        asm volatile("barrier.cluster.arrive.aligned;" ::: "memory");
        asm volatile("barrier.cluster.wait.aligned;" ::: "memory");
    }
}

// ---------------------------------------------------------------------------
extern "C" void kernel_launch(void* const* d_in, const int* in_sizes, int n_in,
                              void* d_out, int out_size) {
    const float* marks = (const float*)d_in[0];
    const float* ts    = (const float*)d_in[1];
    const float* Wemb  = (const float*)d_in[2];
    const float* Wc    = (const float*)d_in[3];
    const float* bc    = (const float*)d_in[4];
    const float* init  = (const float*)d_in[5];
    float* out = (float*)d_out;

    k_embed<<<Bq * Tq, 128>>>(marks, Wemb);
    k_gin<<<dim3((Bq * Tq) / 64, G7 / 128), 256>>>(Wc, bc);
    k_init<<<Bq, 256>>>(init, out);

    const int SMEM = (28672 + 8192 + 8064) * (int)sizeof(float);   // 179,712 B
    cudaFuncSetAttribute(k_recur, cudaFuncAttributeMaxDynamicSharedMemorySize, SMEM);
    cudaFuncSetAttribute(k_recur, cudaFuncAttributeNonPortableClusterSizeAllowed, 1);
    k_recur<<<128, 512, SMEM>>>(Wc, ts, init, out);
}

// round 6
// speedup vs baseline: 1.5497x; 1.5497x over previous
#include <cuda_runtime.h>
#include <cstdint>
#include <math.h>

#define Bq 128
#define Tq 512
#define Cq 100
#define Eq 64
#define Hq 256
#define G7 1792   // 7*H
#define KIN 320   // E+H

typedef unsigned long long ull;

// ---- scratch (device globals; no allocation in kernel_launch) ----
static __device__ float g_r[(size_t)Bq * Tq * Eq];          // rec_input
static __device__ float g_gin[(size_t)Bq * Tq * G7];        // input-side gates (+bias)
static __device__ __align__(16) float g_h[2][Bq][Hq];       // ping-pong h_d [buf][b][j]
static __device__ unsigned g_cnt[8];                        // per-group step counters

__device__ __forceinline__ float sigmf_(float x) { return 1.f / (1.f + expf(-x)); }
__device__ __forceinline__ float softplusf_(float x) {
    return fmaxf(x, 0.f) + log1pf(expf(-fabsf(x)));
}
// fast variants (abs err ~1e-6, budget 1e-3)
__device__ __forceinline__ float sigf(float x) {
    return __fdividef(1.f, 1.f + __expf(-x));
}
__device__ __forceinline__ float tanf_(float x) {
    return 1.f - 2.f * __fdividef(1.f, 1.f + __expf(2.f * x));
}
__device__ __forceinline__ float splusf(float x) {
    return fmaxf(x, 0.f) + __logf(1.f + __expf(-fabsf(x)));
}
__device__ __forceinline__ void fma2_(ull& d, ull a, ull b) {
    asm volatile("fma.rn.f32x2 %0, %1, %2, %0;" : "+l"(d) : "l"(a), "l"(b));
}
__device__ __forceinline__ ull dup2_(float x) {
    ull d;
    asm("mov.b64 %0, {%1, %1};" : "=l"(d) : "f"(x));
    return d;
}
__device__ __forceinline__ float lo_(ull v) { return __uint_as_float((unsigned)v); }
__device__ __forceinline__ float hi_(ull v) { return __uint_as_float((unsigned)(v >> 32)); }

// ---------------------------------------------------------------------------
// K1: rec_input
// ---------------------------------------------------------------------------
__global__ __launch_bounds__(128) void k_embed(const float* __restrict__ marks,
                                               const float* __restrict__ Wemb) {
    int bt = blockIdx.x;
    __shared__ float sm[Cq];
    int tid = threadIdx.x;
    if (tid < Cq) sm[tid] = marks[(size_t)bt * Cq + tid];
    __syncthreads();
    if (tid < Eq) {
        float cnt = 0.f, s = 0.f;
        #pragma unroll
        for (int c = 0; c < Cq; c++) {
            float m = sm[c];
            cnt += m;
            s = fmaf(m, Wemb[c * Eq + tid], s);
        }
        g_r[(size_t)bt * Eq + tid] = s / fmaxf(cnt, 1.f);
    }
}

// ---------------------------------------------------------------------------
// K2: g_gin[bt, j] = g_r[bt,:] @ W_cell[j, 0:64]^T + b_cell[j]   (f32x2)
// ---------------------------------------------------------------------------
__global__ __launch_bounds__(256) void k_gin(const float* __restrict__ Wc,
                                             const float* __restrict__ bc) {
    __shared__ float As[64 * 68];
    __shared__ float Bs[64 * 132];
    int tid = threadIdx.x;
    int row0 = blockIdx.x * 64, col0 = blockIdx.y * 128;

    #pragma unroll
    for (int i = 0; i < 16; i++) {
        int idx = i * 256 + tid;
        int row = idx >> 6, k = idx & 63;
        As[k * 68 + row] = g_r[(size_t)(row0 + row) * Eq + k];
    }
    #pragma unroll
    for (int i = 0; i < 32; i++) {
        int idx = i * 256 + tid;
        int col = idx >> 6, k = idx & 63;
        Bs[k * 132 + col] = Wc[(size_t)(col0 + col) * KIN + k];
    }
    __syncthreads();

    int tx = tid & 15, ty = tid >> 4;
    ull acc2[4][4];
    #pragma unroll
    for (int i = 0; i < 4; i++)
        #pragma unroll
        for (int p = 0; p < 4; p++) acc2[i][p] = 0ull;

    #pragma unroll 4
    for (int k = 0; k < 64; k++) {
        float4 a = *(const float4*)&As[k * 68 + ty * 4];
        ulonglong2 b01 = *(const ulonglong2*)&Bs[k * 132 + tx * 8];
        ulonglong2 b23 = *(const ulonglong2*)&Bs[k * 132 + tx * 8 + 4];
        ull ad[4] = {dup2_(a.x), dup2_(a.y), dup2_(a.z), dup2_(a.w)};
        #pragma unroll
        for (int i = 0; i < 4; i++) {
            fma2_(acc2[i][0], ad[i], b01.x);
            fma2_(acc2[i][1], ad[i], b01.y);
            fma2_(acc2[i][2], ad[i], b23.x);
            fma2_(acc2[i][3], ad[i], b23.y);
        }
    }

    float bb[8];
    #pragma unroll
    for (int jx = 0; jx < 8; jx++) bb[jx] = bc[col0 + tx * 8 + jx];

    #pragma unroll
    for (int i = 0; i < 4; i++) {
        size_t base = (size_t)(row0 + ty * 4 + i) * G7 + col0 + tx * 8;
        float4 o0 = {lo_(acc2[i][0]) + bb[0], hi_(acc2[i][0]) + bb[1],
                     lo_(acc2[i][1]) + bb[2], hi_(acc2[i][1]) + bb[3]};
        float4 o1 = {lo_(acc2[i][2]) + bb[4], hi_(acc2[i][2]) + bb[5],
                     lo_(acc2[i][3]) + bb[6], hi_(acc2[i][3]) + bb[7]};
        *(float4*)&g_gin[base]     = o0;
        *(float4*)&g_gin[base + 4] = o1;
    }
}

// ---------------------------------------------------------------------------
// K3: initial state -> out[b,0,:], g_h[0], reset sync counters
// ---------------------------------------------------------------------------
__global__ __launch_bounds__(256) void k_init(const float* __restrict__ init,
                                              float* __restrict__ out) {
    int b = blockIdx.x, k = threadIdx.x;
    if (b == 0 && k < 8) g_cnt[k] = 0;
    float s0 = init[k], s1 = init[Hq + k], s2 = init[2 * Hq + k];
    float s3 = init[3 * Hq + k], s4 = init[4 * Hq + k], s5 = init[5 * Hq + k];
    float hd0 = tanhf(s0), cd0 = tanhf(s1), cb0 = tanhf(s2), c0 = tanhf(s3);
    float d0 = softplusf_(s4), o0 = sigmf_(s5);
    size_t base = (size_t)b * (Tq + 1) * (6 * Hq);
    out[base + 0 * Hq + k] = hd0;
    out[base + 1 * Hq + k] = o0;
    out[base + 2 * Hq + k] = cb0;
    out[base + 3 * Hq + k] = c0;
    out[base + 4 * Hq + k] = d0;
    out[base + 5 * Hq + k] = cd0;
    g_h[0][b][k] = hd0;
}

// ---------------------------------------------------------------------------
// K4: recurrence. grid = 128 = 8 batch-groups (16 b) x 16 j-slices (16 j).
//   256 threads: tid = s*32 + bg*16 + j  (s:8 k-split, bg:2 b-halves, j:16).
//   Thread tile: 7 gates x 8 batches x 1 j x 32 k, fma.rn.f32x2 packed.
//   Crossbar-minimal: w replication 2 (229KB), h replication 16 but pure
//   16B broadcasts (262KB) -> ~3840 cyc/step ~ FMA2 floor 3584.
//   Phase 2: 1 output/thread, fast-math nonlinearities, decay, writes.
//   h via L2 (stcg/ldcg); R3-proven threadfence+atomic+acquire step barrier.
// ---------------------------------------------------------------------------
__global__ void __launch_bounds__(256, 1)
k_recur(const float* __restrict__ Wc, const float* __restrict__ ts,
        const float* __restrict__ init, float* __restrict__ out) {
    extern __shared__ float sh[];
    float* Ws  = sh;            // 28672 floats: float4 idx (g*64+kq)*16 + j
    float* hs  = sh + 28672;    // 4096 floats:  float4 idx b*64 + kq
    float* red = sh + 32768;    // 16128 floats: [(b*56 + s*7 + g)*18 + j]

    int tid = threadIdx.x;
    int group = blockIdx.x >> 4;     // 0..7
    int rank  = blockIdx.x & 15;     // 0..15
    int j0 = rank * 16;

    // phase-1 identity
    int j1 = tid & 15;
    int bg = (tid >> 4) & 1;
    int s  = tid >> 5;               // 0..7
    int bbase = bg * 8;

    // phase-2 identity: 1 output per thread
    int j2 = tid & 15, b2 = tid >> 4;        // j2:16, b2:16
    int jg2 = j0 + j2;
    int bg2 = group * 16 + b2;

    // one-time weight load (115KB, coalesced-ish along k)
    for (int idx = tid; idx < 7 * 64 * 16 * 4; idx += 256) {
        int e = idx & 3, jw = (idx >> 2) & 15, kq = (idx >> 6) & 63, g = idx >> 12;
        Ws[idx] = Wc[(size_t)(g * Hq + j0 + jw) * KIN + Eq + kq * 4 + e];
    }

    float c_st  = tanhf(init[3 * Hq + jg2]);
    float cb_st = tanhf(init[2 * Hq + jg2]);
    __syncthreads();

    const ulonglong2* WU = (const ulonglong2*)Ws;
    const ulonglong2* HU = (const ulonglong2*)hs;
    float4* hs4 = (float4*)hs;

    for (int t = 0; t < Tq; t++) {
        // ---- stage h (16 b x 256 k = 16KB) from L2, coalesced ----
        const float4* gsrc = (const float4*)&g_h[t & 1][group * 16][0];
        #pragma unroll
        for (int r = 0; r < 4; r++)
            hs4[tid + 256 * r] = __ldcg(gsrc + tid + 256 * r);

        // ---- prefetch input-side gates + timestamps (phase-2 identity) ----
        float ain[7];
        size_t gbase = ((size_t)bg2 * Tq + t) * (size_t)G7 + jg2;
        #pragma unroll
        for (int g = 0; g < 7; g++) ain[g] = __ldcs(&g_gin[gbase + g * Hq]);
        float tc = ts[bg2 * Tq + t];
        float tp = (t > 0) ? ts[bg2 * Tq + t - 1] : 0.f;
        __syncthreads();

        // ---- phase 1: packed-f32x2 GEMM, k-range [s*32, s*32+32) ----
        ull acc[7][8];
        #pragma unroll
        for (int g = 0; g < 7; g++)
            #pragma unroll
            for (int bi = 0; bi < 8; bi++) acc[g][bi] = 0ull;

        #pragma unroll
        for (int q = 0; q < 8; q++) {
            int kq = s * 8 + q;
            ulonglong2 hv[8];
            #pragma unroll
            for (int bi = 0; bi < 8; bi++)
                hv[bi] = HU[(bbase + bi) * 64 + kq];
            #pragma unroll
            for (int g = 0; g < 7; g++) {
                ulonglong2 wv = WU[(g * 64 + kq) * 16 + j1];
                #pragma unroll
                for (int bi = 0; bi < 8; bi++) {
                    fma2_(acc[g][bi], wv.x, hv[bi].x);
                    fma2_(acc[g][bi], wv.y, hv[bi].y);
                }
            }
        }

        // ---- store k-partials (conflict-free: b-coeff = 1008 = 16 mod 32) ----
        #pragma unroll
        for (int g = 0; g < 7; g++)
            #pragma unroll
            for (int bi = 0; bi < 8; bi++)
                red[((bbase + bi) * 56 + s * 7 + g) * 18 + j1] =
                    lo_(acc[g][bi]) + hi_(acc[g][bi]);
        __syncthreads();

        // ---- phase 2: reduce 8 partials + nonlinearities + decay + writes ----
        {
            float gate[7];
            #pragma unroll
            for (int g = 0; g < 7; g++) {
                float v = ain[g];
                #pragma unroll
                for (int sp = 0; sp < 8; sp++)
                    v += red[(b2 * 56 + sp * 7 + g) * 18 + j2];
                gate[g] = v;
            }

            float gi  = sigf(gate[0]);
            float gf  = sigf(gate[1]);
            float gz  = tanf_(gate[2]);
            float go  = sigf(gate[3]);
            float gib = sigf(gate[4]);
            float gfb = sigf(gate[5]);
            float gd  = splusf(gate[6]);
            float dt  = tc - tp;

            float ct  = gf * c_st + gi * gz;
            float cbt = gfb * cb_st + gib * gz;
            float cdt = cbt + (ct - cbt) * __expf(-gd * dt);
            float hdt = go * tanf_(cdt);

            size_t ob = ((size_t)bg2 * (Tq + 1) + t + 1) * (size_t)(6 * Hq) + jg2;
            __stcs(&out[ob + 0 * Hq], hdt);
            __stcs(&out[ob + 1 * Hq], go);
            __stcs(&out[ob + 2 * Hq], cbt);
            __stcs(&out[ob + 3 * Hq], ct);
            __stcs(&out[ob + 4 * Hq], gd);
            __stcs(&out[ob + 5 * Hq], cdt);

            c_st = ct; cb_st = cbt;
            __stcg(&g_h[(t & 1) ^ 1][bg2][jg2], hdt);
        }

        // ---- per-group step barrier (R3-proven) ----
        __threadfence();
        __syncthreads();
        if (tid == 0) {
            atomicAdd(&g_cnt[group], 1u);
            unsigned target = 16u * (unsigned)(t + 1), v;
            do {
                asm volatile("ld.acquire.gpu.u32 %0, [%1];"
                             : "=r"(v) : "l"(g_cnt + group) : "memory");
            } while (v < target);
        }
        __syncthreads();
    }
}

// ---------------------------------------------------------------------------
extern "C" void kernel_launch(void* const* d_in, const int* in_sizes, int n_in,
                              void* d_out, int out_size) {
    const float* marks = (const float*)d_in[0];
    const float* ts    = (const float*)d_in[1];
    const float* Wemb  = (const float*)d_in[2];
    const float* Wc    = (const float*)d_in[3];
    const float* bc    = (const float*)d_in[4];
    const float* init  = (const float*)d_in[5];
    float* out = (float*)d_out;

    k_embed<<<Bq * Tq, 128>>>(marks, Wemb);
    k_gin<<<dim3((Bq * Tq) / 64, G7 / 128), 256>>>(Wc, bc);
    k_init<<<Bq, 256>>>(init, out);

    const int SMEM = (28672 + 4096 + 16128) * (int)sizeof(float);   // 195,584 B
    cudaFuncSetAttribute(k_recur, cudaFuncAttributeMaxDynamicSharedMemorySize, SMEM);
    k_recur<<<128, 256, SMEM>>>(Wc, ts, init, out);
}

// round 7
// speedup vs baseline: 1.5981x; 1.0312x over previous
#include <cuda_runtime.h>
#include <cstdint>
#include <math.h>

#define Bq 128
#define Tq 512
#define Cq 100
#define Eq 64
#define Hq 256
#define KIN 320   // E+H

typedef unsigned long long ull;

// ---- scratch (device globals; no allocation in kernel_launch) ----
static __device__ float g_r[(size_t)Bq * Tq * Eq];          // rec_input
static __device__ __align__(16) float g_h[2][Bq][Hq];       // ping-pong h_d [buf][b][j]
static __device__ unsigned g_cnt[16];                       // [stream*8 + group]

__device__ __forceinline__ float sigmf_(float x) { return 1.f / (1.f + expf(-x)); }
__device__ __forceinline__ float softplusf_(float x) {
    return fmaxf(x, 0.f) + log1pf(expf(-fabsf(x)));
}
// fast variants (abs err ~1e-6, budget 1e-3)
__device__ __forceinline__ float sigf(float x) {
    return __fdividef(1.f, 1.f + __expf(-x));
}
__device__ __forceinline__ float tanf_(float x) {
    return 1.f - 2.f * __fdividef(1.f, 1.f + __expf(2.f * x));
}
__device__ __forceinline__ float splusf(float x) {
    return fmaxf(x, 0.f) + __logf(1.f + __expf(-fabsf(x)));
}
__device__ __forceinline__ void fma2_(ull& d, ull a, ull b) {
    asm volatile("fma.rn.f32x2 %0, %1, %2, %0;" : "+l"(d) : "l"(a), "l"(b));
}
__device__ __forceinline__ float lo_(ull v) { return __uint_as_float((unsigned)v); }
__device__ __forceinline__ float hi_(ull v) { return __uint_as_float((unsigned)(v >> 32)); }

// ---------------------------------------------------------------------------
// K1: rec_input[b,t,e] = (marks[b,t,:] @ W_emb[:,e]) / max(sum(marks),1)
// ---------------------------------------------------------------------------
__global__ __launch_bounds__(128) void k_embed(const float* __restrict__ marks,
                                               const float* __restrict__ Wemb) {
    int bt = blockIdx.x;
    __shared__ float sm[Cq];
    int tid = threadIdx.x;
    if (tid < Cq) sm[tid] = marks[(size_t)bt * Cq + tid];
    __syncthreads();
    if (tid < Eq) {
        float cnt = 0.f, s = 0.f;
        #pragma unroll
        for (int c = 0; c < Cq; c++) {
            float m = sm[c];
            cnt += m;
            s = fmaf(m, Wemb[c * Eq + tid], s);
        }
        g_r[(size_t)bt * Eq + tid] = s / fmaxf(cnt, 1.f);
    }
}

// ---------------------------------------------------------------------------
// K3: initial state -> out[b,0,:], g_h[0], reset sync counters
// ---------------------------------------------------------------------------
__global__ __launch_bounds__(256) void k_init(const float* __restrict__ init,
                                              float* __restrict__ out) {
    int b = blockIdx.x, k = threadIdx.x;
    if (b == 0 && k < 16) g_cnt[k] = 0;
    float s0 = init[k], s1 = init[Hq + k], s2 = init[2 * Hq + k];
    float s3 = init[3 * Hq + k], s4 = init[4 * Hq + k], s5 = init[5 * Hq + k];
    float hd0 = tanhf(s0), cd0 = tanhf(s1), cb0 = tanhf(s2), c0 = tanhf(s3);
    float d0 = softplusf_(s4), o0 = sigmf_(s5);
    size_t base = (size_t)b * (Tq + 1) * (6 * Hq);
    out[base + 0 * Hq + k] = hd0;
    out[base + 1 * Hq + k] = o0;
    out[base + 2 * Hq + k] = cb0;
    out[base + 3 * Hq + k] = c0;
    out[base + 4 * Hq + k] = d0;
    out[base + 5 * Hq + k] = cd0;
    g_h[0][b][k] = hd0;
}

// ---------------------------------------------------------------------------
// K4: fused recurrence (input GEMM folded in, K = 256 h + 64 r).
//   grid = 128 = 8 batch-groups (16 b) x 16 j-slices (16 j).
//   TWO interleaved batch streams of 8 b each: while stream A's release
//   propagates through L2 to the other 15 CTAs, the CTA computes stream B.
//   GEMM identity: tid = s*32 + bg*16 + j1 (s:8 k-split, bg:2, j1:16);
//   thread tile 7 g x 4 b, fma.rn.f32x2 packed along k.
//   Phase 2 (tid<128): reduce 8 k-partials + bias, fast-math gates, decay.
//   Barrier: CG pattern — bar.sync, tid0 red.release.gpu, all threads
//   ld.acquire.gpu poll at next use; out STGs issued after the release.
// ---------------------------------------------------------------------------
__global__ void __launch_bounds__(256, 1)
k_recur(const float* __restrict__ Wc, const float* __restrict__ ts,
        const float* __restrict__ init, const float* __restrict__ bc,
        float* __restrict__ out) {
    extern __shared__ float sh[];
    float* Ws  = sh;            // 28672: h-weights  ((g*64+kq)*16 + jw)*4 + e
    float* Wr  = sh + 28672;    //  7168: r-weights  ((g*16+rq)*16 + jw)*4 + e
    float* hs  = sh + 35840;    //  2048: staged h   float4 idx b*64 + kq
    float* rs  = sh + 37888;    //   512: staged r   float4 idx b*16 + rq
    float* red = sh + 38400;    //  9184: partials   (s*7+g)*164 + b*20 + j
    float* bs  = sh + 47584;    //   112: bias       g*16 + j

    int tid = threadIdx.x;
    int group = blockIdx.x >> 4;     // 0..7
    int rank  = blockIdx.x & 15;     // 0..15
    int j0 = rank * 16;

    // phase-1 identity
    int j1 = tid & 15;
    int bg = (tid >> 4) & 1;
    int s  = tid >> 5;               // 0..7
    int bbase = bg * 4;

    // phase-2 identity (tid < 128)
    int j2 = tid & 15, b2 = tid >> 4;    // b2 0..7
    int jg = j0 + j2;
    bool p2 = tid < 128;

    // one-time weight/bias loads
    for (int idx = tid; idx < 28672; idx += 256) {
        int e = idx & 3, jw = (idx >> 2) & 15, kq = (idx >> 6) & 63, g = idx >> 12;
        Ws[idx] = Wc[(size_t)(g * Hq + j0 + jw) * KIN + Eq + kq * 4 + e];
    }
    for (int idx = tid; idx < 7168; idx += 256) {
        int e = idx & 3, jw = (idx >> 2) & 15, rq = (idx >> 6) & 15, g = idx >> 10;
        Wr[idx] = Wc[(size_t)(g * Hq + j0 + jw) * KIN + rq * 4 + e];
    }
    if (tid < 112) bs[tid] = bc[(tid >> 4) * Hq + j0 + (tid & 15)];

    float c_st[2], cb_st[2];
    if (p2) {
        float ci  = tanhf(init[3 * Hq + jg]);
        float cbi = tanhf(init[2 * Hq + jg]);
        c_st[0] = c_st[1] = ci;
        cb_st[0] = cb_st[1] = cbi;
    }
    __syncthreads();

    const ulonglong2* WU  = (const ulonglong2*)Ws;
    const ulonglong2* WrU = (const ulonglong2*)Wr;
    const ulonglong2* HU  = (const ulonglong2*)hs;
    const ulonglong2* RU  = (const ulonglong2*)rs;
    float4* hs4 = (float4*)hs;
    float4* rs4 = (float4*)rs;
    const float4* gr4 = (const float4*)g_r;

    for (int t = 0; t < Tq; t++) {
        #pragma unroll
        for (int S = 0; S < 2; S++) {
            int gb0 = group * 16 + S * 8;
            unsigned* cnt = g_cnt + S * 8 + group;

            // ---- acquire: wait for all 16 CTAs' h of (t-1) for this stream ----
            unsigned target = 16u * (unsigned)t, v;
            do {
                asm volatile("ld.acquire.gpu.u32 %0, [%1];"
                             : "=r"(v) : "l"(cnt) : "memory");
            } while (v < target);

            // ---- stage h (8 b x 256 k) + r (8 b x 64) ----
            const float4* gsrc = (const float4*)&g_h[t & 1][0][0];
            {
                int i = tid, b = i >> 6, kq = i & 63;
                hs4[i] = __ldcg(gsrc + (size_t)(gb0 + b) * 64 + kq);
                i = tid + 256; b = i >> 6; kq = i & 63;
                hs4[i] = __ldcg(gsrc + (size_t)(gb0 + b) * 64 + kq);
            }
            float tc = 0.f, tp = 0.f;
            if (p2) {
                int b = tid >> 4, rq = tid & 15;
                rs4[tid] = gr4[((size_t)(gb0 + b) * Tq + t) * 16 + rq];
                tc = ts[(gb0 + b2) * Tq + t];
                tp = (t > 0) ? ts[(gb0 + b2) * Tq + t - 1] : 0.f;
            }
            __syncthreads();

            // ---- GEMM: 7 g x 4 b, k-split s, packed f32x2 ----
            ull acc[7][4];
            #pragma unroll
            for (int g = 0; g < 7; g++)
                #pragma unroll
                for (int bi = 0; bi < 4; bi++) acc[g][bi] = 0ull;

            #pragma unroll
            for (int q = 0; q < 8; q++) {
                int kq = s * 8 + q;
                ulonglong2 hv[4];
                #pragma unroll
                for (int bi = 0; bi < 4; bi++)
                    hv[bi] = HU[(bbase + bi) * 64 + kq];
                #pragma unroll
                for (int g = 0; g < 7; g++) {
                    ulonglong2 wv = WU[(g * 64 + kq) * 16 + j1];
                    #pragma unroll
                    for (int bi = 0; bi < 4; bi++) {
                        fma2_(acc[g][bi], wv.x, hv[bi].x);
                        fma2_(acc[g][bi], wv.y, hv[bi].y);
                    }
                }
            }
            #pragma unroll
            for (int r2 = 0; r2 < 2; r2++) {
                int rq = s * 2 + r2;
                ulonglong2 rv[4];
                #pragma unroll
                for (int bi = 0; bi < 4; bi++)
                    rv[bi] = RU[(bbase + bi) * 16 + rq];
                #pragma unroll
                for (int g = 0; g < 7; g++) {
                    ulonglong2 wv = WrU[(g * 16 + rq) * 16 + j1];
                    #pragma unroll
                    for (int bi = 0; bi < 4; bi++) {
                        fma2_(acc[g][bi], wv.x, rv[bi].x);
                        fma2_(acc[g][bi], wv.y, rv[bi].y);
                    }
                }
            }

            // ---- store k-partials (conflict-free: b-coeff 20) ----
            #pragma unroll
            for (int g = 0; g < 7; g++)
                #pragma unroll
                for (int bi = 0; bi < 4; bi++)
                    red[(s * 7 + g) * 164 + (bbase + bi) * 20 + j1] =
                        lo_(acc[g][bi]) + hi_(acc[g][bi]);
            __syncthreads();

            // ---- phase 2 ----
            float hdt = 0.f, go = 0.f, cbt = 0.f, ct = 0.f, gd = 0.f, cdt = 0.f;
            if (p2) {
                float gate[7];
                #pragma unroll
                for (int g = 0; g < 7; g++) {
                    float vv = bs[g * 16 + j2];
                    #pragma unroll
                    for (int sp = 0; sp < 8; sp++)
                        vv += red[(sp * 7 + g) * 164 + b2 * 20 + j2];
                    gate[g] = vv;
                }
                float gi  = sigf(gate[0]);
                float gf  = sigf(gate[1]);
                float gz  = tanf_(gate[2]);
                go        = sigf(gate[3]);
                float gib = sigf(gate[4]);
                float gfb = sigf(gate[5]);
                gd        = splusf(gate[6]);
                float dt  = tc - tp;

                ct  = gf * c_st[S] + gi * gz;
                cbt = gfb * cb_st[S] + gib * gz;
                cdt = cbt + (ct - cbt) * __expf(-gd * dt);
                hdt = go * tanf_(cdt);

                c_st[S] = ct; cb_st[S] = cbt;
                __stcg(&g_h[(t & 1) ^ 1][gb0 + b2][jg], hdt);
            }

            // ---- release: bar orders all threads' stcg, tid0 publishes ----
            __syncthreads();
            if (tid == 0)
                asm volatile("red.release.gpu.global.add.u32 [%0], %1;"
                             :: "l"(cnt), "r"(1u) : "memory");

            // ---- out writes AFTER release (latency hidden by next stream) ----
            if (p2) {
                size_t ob = ((size_t)(gb0 + b2) * (Tq + 1) + t + 1) * (size_t)(6 * Hq) + jg;
                __stcs(&out[ob + 0 * Hq], hdt);
                __stcs(&out[ob + 1 * Hq], go);
                __stcs(&out[ob + 2 * Hq], cbt);
                __stcs(&out[ob + 3 * Hq], ct);
                __stcs(&out[ob + 4 * Hq], gd);
                __stcs(&out[ob + 5 * Hq], cdt);
            }
        }
    }
}

// ---------------------------------------------------------------------------
extern "C" void kernel_launch(void* const* d_in, const int* in_sizes, int n_in,
                              void* d_out, int out_size) {
    const float* marks = (const float*)d_in[0];
    const float* ts    = (const float*)d_in[1];
    const float* Wemb  = (const float*)d_in[2];
    const float* Wc    = (const float*)d_in[3];
    const float* bc    = (const float*)d_in[4];
    const float* init  = (const float*)d_in[5];
    float* out = (float*)d_out;

    k_embed<<<Bq * Tq, 128>>>(marks, Wemb);
    k_init<<<Bq, 256>>>(init, out);

    const int SMEM = 47696 * (int)sizeof(float);   // 190,784 B
    cudaFuncSetAttribute(k_recur, cudaFuncAttributeMaxDynamicSharedMemorySize, SMEM);
    k_recur<<<128, 256, SMEM>>>(Wc, ts, init, bc, out);
}

// round 8
// speedup vs baseline: 1.7151x; 1.0732x over previous
#include <cuda_runtime.h>
#include <cstdint>
#include <math.h>

#define Bq 128
#define Tq 512
#define Cq 100
#define Eq 64
#define Hq 256
#define KIN 320   // E+H

typedef unsigned long long ull;

// ---- scratch (device globals; no allocation in kernel_launch) ----
static __device__ float g_r[(size_t)Bq * Tq * Eq];          // rec_input
static __device__ __align__(16) float g_h[2][Bq][Hq];       // ping-pong h_d [buf][b][j]
static __device__ unsigned g_cnt[16];                       // [stream*8 + group]

__device__ __forceinline__ float sigmf_(float x) { return 1.f / (1.f + expf(-x)); }
__device__ __forceinline__ float softplusf_(float x) {
    return fmaxf(x, 0.f) + log1pf(expf(-fabsf(x)));
}
// fast variants (abs err ~1e-6, budget 1e-3)
__device__ __forceinline__ float sigf(float x) {
    return __fdividef(1.f, 1.f + __expf(-x));
}
__device__ __forceinline__ float tanf_(float x) {
    return 1.f - 2.f * __fdividef(1.f, 1.f + __expf(2.f * x));
}
__device__ __forceinline__ float splusf(float x) {
    return fmaxf(x, 0.f) + __logf(1.f + __expf(-fabsf(x)));
}
__device__ __forceinline__ void fma2_(ull& d, ull a, ull b) {
    asm volatile("fma.rn.f32x2 %0, %1, %2, %0;" : "+l"(d) : "l"(a), "l"(b));
}
__device__ __forceinline__ float lo_(ull v) { return __uint_as_float((unsigned)v); }
__device__ __forceinline__ float hi_(ull v) { return __uint_as_float((unsigned)(v >> 32)); }

// ---------------------------------------------------------------------------
// K1: rec_input[b,t,e] = (marks[b,t,:] @ W_emb[:,e]) / max(sum(marks),1)
// ---------------------------------------------------------------------------
__global__ __launch_bounds__(128) void k_embed(const float* __restrict__ marks,
                                               const float* __restrict__ Wemb) {
    int bt = blockIdx.x;
    __shared__ float sm[Cq];
    int tid = threadIdx.x;
    if (tid < Cq) sm[tid] = marks[(size_t)bt * Cq + tid];
    __syncthreads();
    if (tid < Eq) {
        float cnt = 0.f, s = 0.f;
        #pragma unroll
        for (int c = 0; c < Cq; c++) {
            float m = sm[c];
            cnt += m;
            s = fmaf(m, Wemb[c * Eq + tid], s);
        }
        g_r[(size_t)bt * Eq + tid] = s / fmaxf(cnt, 1.f);
    }
}

// ---------------------------------------------------------------------------
// K3: initial state -> out[b,0,:], g_h[0], reset sync counters
// ---------------------------------------------------------------------------
__global__ __launch_bounds__(256) void k_init(const float* __restrict__ init,
                                              float* __restrict__ out) {
    int b = blockIdx.x, k = threadIdx.x;
    if (b == 0 && k < 16) g_cnt[k] = 0;
    float s0 = init[k], s1 = init[Hq + k], s2 = init[2 * Hq + k];
    float s3 = init[3 * Hq + k], s4 = init[4 * Hq + k], s5 = init[5 * Hq + k];
    float hd0 = tanhf(s0), cd0 = tanhf(s1), cb0 = tanhf(s2), c0 = tanhf(s3);
    float d0 = softplusf_(s4), o0 = sigmf_(s5);
    size_t base = (size_t)b * (Tq + 1) * (6 * Hq);
    out[base + 0 * Hq + k] = hd0;
    out[base + 1 * Hq + k] = o0;
    out[base + 2 * Hq + k] = cb0;
    out[base + 3 * Hq + k] = c0;
    out[base + 4 * Hq + k] = d0;
    out[base + 5 * Hq + k] = cd0;
    g_h[0][b][k] = hd0;
}

// ---------------------------------------------------------------------------
// K4: fused recurrence, software-pipelined dual stream.
//   grid = 128 = 8 batch-groups (16 b) x 16 j-slices (16 j). 256 threads.
//   Per half-step: STS prefetched h/r regs -> bar -> GEMM (7g x 4b x k-split 8,
//   fma.rn.f32x2) -> red STS -> bar -> [poll+ldcg NEXT stream's h/r into regs]
//   -> phase2 (tid<128): reduce, gates, decay, stcg h -> bar.sync 1,128 ->
//   tid0 red.release -> STG outs. ldcg latency hides under GEMM/phase2.
// ---------------------------------------------------------------------------
__global__ void __launch_bounds__(256, 1)
k_recur(const float* __restrict__ Wc, const float* __restrict__ ts,
        const float* __restrict__ init, const float* __restrict__ bc,
        float* __restrict__ out) {
    extern __shared__ float sh[];
    float* Ws  = sh;            // 28672: h-weights  ((g*64+kq)*16 + jw)*4 + e
    float* Wr  = sh + 28672;    //  7168: r-weights  ((g*16+rq)*16 + jw)*4 + e
    float* hs  = sh + 35840;    //  2048: staged h   float4 idx b*64 + kq
    float* rs  = sh + 37888;    //   512: staged r   float4 idx b*16 + rq
    float* red = sh + 38400;    //  9184: partials   (s*7+g)*164 + b*20 + j
    float* bs  = sh + 47584;    //   112: bias       g*16 + j

    int tid = threadIdx.x;
    int group = blockIdx.x >> 4;     // 0..7
    int rank  = blockIdx.x & 15;     // 0..15
    int j0 = rank * 16;

    // phase-1 identity
    int j1 = tid & 15;
    int bg = (tid >> 4) & 1;
    int s  = tid >> 5;               // 0..7
    int bbase = bg * 4;

    // phase-2 identity (tid < 128)
    int j2 = tid & 15, b2 = tid >> 4;    // b2 0..7
    int jg = j0 + j2;
    bool p2 = tid < 128;

    // one-time weight/bias loads
    for (int idx = tid; idx < 28672; idx += 256) {
        int e = idx & 3, jw = (idx >> 2) & 15, kq = (idx >> 6) & 63, g = idx >> 12;
        Ws[idx] = Wc[(size_t)(g * Hq + j0 + jw) * KIN + Eq + kq * 4 + e];
    }
    for (int idx = tid; idx < 7168; idx += 256) {
        int e = idx & 3, jw = (idx >> 2) & 15, rq = (idx >> 6) & 15, g = idx >> 10;
        Wr[idx] = Wc[(size_t)(g * Hq + j0 + jw) * KIN + rq * 4 + e];
    }
    if (tid < 112) bs[tid] = bc[(tid >> 4) * Hq + j0 + (tid & 15)];

    float c_st[2], cb_st[2];
    if (p2) {
        float ci  = tanhf(init[3 * Hq + jg]);
        float cbi = tanhf(init[2 * Hq + jg]);
        c_st[0] = c_st[1] = ci;
        cb_st[0] = cb_st[1] = cbi;
    }
    __syncthreads();

    const ulonglong2* WU  = (const ulonglong2*)Ws;
    const ulonglong2* WrU = (const ulonglong2*)Wr;
    const ulonglong2* HU  = (const ulonglong2*)hs;
    const ulonglong2* RU  = (const ulonglong2*)rs;
    float4* hs4 = (float4*)hs;
    float4* rs4 = (float4*)rs;
    const float4* gr4 = (const float4*)g_r;

    // staging-load indices
    int b_i1 = tid >> 6,          kq_i1 = tid & 63;
    int b_i2 = (tid + 256) >> 6,  kq_i2 = tid & 63;
    int rb   = tid >> 4,          rqq   = tid & 15;   // tid<128

    // prefetch registers
    float4 ph0, ph1, pr;
    float ptc = 0.f, ptp = 0.f;

    // prologue: load stream 0, t=0 (h(0) from k_init; counters start at 0)
    {
        int gb0 = group * 16;
        const float4* gsrc = (const float4*)&g_h[0][0][0];
        ph0 = __ldcg(gsrc + (gb0 + b_i1) * 64 + kq_i1);
        ph1 = __ldcg(gsrc + (gb0 + b_i2) * 64 + kq_i2);
        if (p2) {
            pr  = gr4[((size_t)(gb0 + rb) * Tq + 0) * 16 + rqq];
            ptc = ts[(gb0 + b2) * Tq + 0];
            ptp = 0.f;
        }
    }

    for (int t = 0; t < Tq; t++) {
        #pragma unroll
        for (int S = 0; S < 2; S++) {
            int gb0 = group * 16 + S * 8;

            // ---- stage from prefetch regs ----
            hs4[tid]       = ph0;
            hs4[tid + 256] = ph1;
            float tc = ptc, tp = ptp;
            if (p2) rs4[tid] = pr;
            __syncthreads();

            // ---- GEMM: 7 g x 4 b, k-split s, packed f32x2 ----
            ull acc[7][4];
            #pragma unroll
            for (int g = 0; g < 7; g++)
                #pragma unroll
                for (int bi = 0; bi < 4; bi++) acc[g][bi] = 0ull;

            #pragma unroll
            for (int q = 0; q < 8; q++) {
                int kq = s * 8 + q;
                ulonglong2 hv[4];
                #pragma unroll
                for (int bi = 0; bi < 4; bi++)
                    hv[bi] = HU[(bbase + bi) * 64 + kq];
                #pragma unroll
                for (int g = 0; g < 7; g++) {
                    ulonglong2 wv = WU[(g * 64 + kq) * 16 + j1];
                    #pragma unroll
                    for (int bi = 0; bi < 4; bi++) {
                        fma2_(acc[g][bi], wv.x, hv[bi].x);
                        fma2_(acc[g][bi], wv.y, hv[bi].y);
                    }
                }
            }
            #pragma unroll
            for (int r2 = 0; r2 < 2; r2++) {
                int rq = s * 2 + r2;
                ulonglong2 rv[4];
                #pragma unroll
                for (int bi = 0; bi < 4; bi++)
                    rv[bi] = RU[(bbase + bi) * 16 + rq];
                #pragma unroll
                for (int g = 0; g < 7; g++) {
                    ulonglong2 wv = WrU[(g * 16 + rq) * 16 + j1];
                    #pragma unroll
                    for (int bi = 0; bi < 4; bi++) {
                        fma2_(acc[g][bi], wv.x, rv[bi].x);
                        fma2_(acc[g][bi], wv.y, rv[bi].y);
                    }
                }
            }

            // ---- store k-partials ----
            #pragma unroll
            for (int g = 0; g < 7; g++)
                #pragma unroll
                for (int bi = 0; bi < 4; bi++)
                    red[(s * 7 + g) * 164 + (bbase + bi) * 20 + j1] =
                        lo_(acc[g][bi]) + hi_(acc[g][bi]);
            __syncthreads();

            // ---- prefetch next stream's h/r (poll + ldcg; hides under phase2) ----
            bool doPref = !(S == 1 && t == Tq - 1);
            if (doPref) {
                int nS = S ^ 1;
                int nt = S ? t + 1 : t;          // step whose GEMM will consume
                unsigned* cnt = g_cnt + nS * 8 + group;
                unsigned target = 16u * (unsigned)nt, v;
                do {
                    asm volatile("ld.acquire.gpu.u32 %0, [%1];"
                                 : "=r"(v) : "l"(cnt) : "memory");
                } while (v < target);

                int ngb0 = group * 16 + nS * 8;
                const float4* gsrc = (const float4*)&g_h[nt & 1][0][0];
                ph0 = __ldcg(gsrc + (ngb0 + b_i1) * 64 + kq_i1);
                ph1 = __ldcg(gsrc + (ngb0 + b_i2) * 64 + kq_i2);
                if (p2) {
                    pr  = gr4[((size_t)(ngb0 + rb) * Tq + nt) * 16 + rqq];
                    ptc = ts[(ngb0 + b2) * Tq + nt];
                    ptp = (nt > 0) ? ts[(ngb0 + b2) * Tq + nt - 1] : 0.f;
                }
            }

            // ---- phase 2 (tid<128): reduce + gates + decay + writes ----
            if (p2) {
                float gate[7];
                #pragma unroll
                for (int g = 0; g < 7; g++) {
                    float vv = bs[g * 16 + j2];
                    #pragma unroll
                    for (int sp = 0; sp < 8; sp++)
                        vv += red[(sp * 7 + g) * 164 + b2 * 20 + j2];
                    gate[g] = vv;
                }
                float gi  = sigf(gate[0]);
                float gf  = sigf(gate[1]);
                float gz  = tanf_(gate[2]);
                float go  = sigf(gate[3]);
                float gib = sigf(gate[4]);
                float gfb = sigf(gate[5]);
                float gd  = splusf(gate[6]);
                float dt  = tc - tp;

                float ct  = gf * c_st[S] + gi * gz;
                float cbt = gfb * cb_st[S] + gib * gz;
                float cdt = cbt + (ct - cbt) * __expf(-gd * dt);
                float hdt = go * tanf_(cdt);

                c_st[S] = ct; cb_st[S] = cbt;
                __stcg(&g_h[(t & 1) ^ 1][gb0 + b2][jg], hdt);

                // partial barrier over phase2 warps, then publish
                asm volatile("bar.sync 1, 128;" ::: "memory");
                if (tid == 0)
                    asm volatile("red.release.gpu.global.add.u32 [%0], %1;"
                                 :: "l"(g_cnt + S * 8 + group), "r"(1u) : "memory");

                size_t ob = ((size_t)(gb0 + b2) * (Tq + 1) + t + 1) * (size_t)(6 * Hq) + jg;
                __stcs(&out[ob + 0 * Hq], hdt);
                __stcs(&out[ob + 1 * Hq], go);
                __stcs(&out[ob + 2 * Hq], cbt);
                __stcs(&out[ob + 3 * Hq], ct);
                __stcs(&out[ob + 4 * Hq], gd);
                __stcs(&out[ob + 5 * Hq], cdt);
            }
            // next half-step's stage bar separates red reads from next red writes
        }
    }
}

// ---------------------------------------------------------------------------
extern "C" void kernel_launch(void* const* d_in, const int* in_sizes, int n_in,
                              void* d_out, int out_size) {
    const float* marks = (const float*)d_in[0];
    const float* ts    = (const float*)d_in[1];
    const float* Wemb  = (const float*)d_in[2];
    const float* Wc    = (const float*)d_in[3];
    const float* bc    = (const float*)d_in[4];
    const float* init  = (const float*)d_in[5];
    float* out = (float*)d_out;

    k_embed<<<Bq * Tq, 128>>>(marks, Wemb);
    k_init<<<Bq, 256>>>(init, out);

    const int SMEM = 47696 * (int)sizeof(float);   // 190,784 B
    cudaFuncSetAttribute(k_recur, cudaFuncAttributeMaxDynamicSharedMemorySize, SMEM);
    k_recur<<<128, 256, SMEM>>>(Wc, ts, init, bc, out);
}

// round 9
// speedup vs baseline: 2.0243x; 1.1803x over previous
#include <cuda_runtime.h>
#include <cstdint>
#include <math.h>

#define Bq 128
#define Tq 512
#define Cq 100
#define Eq 64
#define Hq 256
#define KIN 320   // E+H

typedef unsigned long long ull;

// ---- scratch (device globals; no allocation in kernel_launch) ----
static __device__ float g_r[(size_t)Bq * Tq * Eq];          // rec_input
static __device__ __align__(16) float g_h[2][Bq][Hq];       // ping-pong h_d [buf][b][j]
static __device__ unsigned g_cnt[16];                       // [stream*8 + group]

__device__ __forceinline__ float sigmf_(float x) { return 1.f / (1.f + expf(-x)); }
__device__ __forceinline__ float softplusf_(float x) {
    return fmaxf(x, 0.f) + log1pf(expf(-fabsf(x)));
}
// fast variants (abs err ~1e-6, budget 1e-3)
__device__ __forceinline__ float sigf(float x) {
    return __fdividef(1.f, 1.f + __expf(-x));
}
__device__ __forceinline__ float tanf_(float x) {
    return 1.f - 2.f * __fdividef(1.f, 1.f + __expf(2.f * x));
}
__device__ __forceinline__ float splusf(float x) {
    return fmaxf(x, 0.f) + __logf(1.f + __expf(-fabsf(x)));
}
__device__ __forceinline__ void fma2_(ull& d, ull a, ull b) {
    asm volatile("fma.rn.f32x2 %0, %1, %2, %0;" : "+l"(d) : "l"(a), "l"(b));
}
__device__ __forceinline__ float lo_(ull v) { return __uint_as_float((unsigned)v); }
__device__ __forceinline__ float hi_(ull v) { return __uint_as_float((unsigned)(v >> 32)); }

// ---------------------------------------------------------------------------
// K1: rec_input[b,t,e] = (marks[b,t,:] @ W_emb[:,e]) / max(sum(marks),1)
// ---------------------------------------------------------------------------
__global__ __launch_bounds__(128) void k_embed(const float* __restrict__ marks,
                                               const float* __restrict__ Wemb) {
    int bt = blockIdx.x;
    __shared__ float sm[Cq];
    int tid = threadIdx.x;
    if (tid < Cq) sm[tid] = marks[(size_t)bt * Cq + tid];
    __syncthreads();
    if (tid < Eq) {
        float cnt = 0.f, s = 0.f;
        #pragma unroll
        for (int c = 0; c < Cq; c++) {
            float m = sm[c];
            cnt += m;
            s = fmaf(m, Wemb[c * Eq + tid], s);
        }
        g_r[(size_t)bt * Eq + tid] = s / fmaxf(cnt, 1.f);
    }
}

// ---------------------------------------------------------------------------
// K3: initial state -> out[b,0,:], g_h[0], reset sync counters
// ---------------------------------------------------------------------------
__global__ __launch_bounds__(256) void k_init(const float* __restrict__ init,
                                              float* __restrict__ out) {
    int b = blockIdx.x, k = threadIdx.x;
    if (b == 0 && k < 16) g_cnt[k] = 0;
    float s0 = init[k], s1 = init[Hq + k], s2 = init[2 * Hq + k];
    float s3 = init[3 * Hq + k], s4 = init[4 * Hq + k], s5 = init[5 * Hq + k];
    float hd0 = tanhf(s0), cd0 = tanhf(s1), cb0 = tanhf(s2), c0 = tanhf(s3);
    float d0 = softplusf_(s4), o0 = sigmf_(s5);
    size_t base = (size_t)b * (Tq + 1) * (6 * Hq);
    out[base + 0 * Hq + k] = hd0;
    out[base + 1 * Hq + k] = o0;
    out[base + 2 * Hq + k] = cb0;
    out[base + 3 * Hq + k] = c0;
    out[base + 4 * Hq + k] = d0;
    out[base + 5 * Hq + k] = cd0;
    g_h[0][b][k] = hd0;
}

// ---------------------------------------------------------------------------
// K4: fused recurrence, WARP-SPECIALIZED dual stream.
//   grid = 128 = 8 batch-groups (16 b) x 16 j-slices (16 j). 256 threads.
//   Warps 0-3 = stream A (group's b 0..7), warps 4-7 = stream B (b 8..15).
//   SMSP i hosts warp i (A) + warp i+4 (B): when one stream stalls
//   (poll / L2 / barrier), the other issues FMA2.
//   Per stream: 128 threads, tid = s*32 + bg*16 + j1 (s:4 k-split of 80,
//   bg:2, j1:16); thread tile 7 g x 4 b, fma.rn.f32x2. Named barrier
//   (1+stream, 128) only couples the stream's own warps.
//   Phase 2: 1 output/thread. Register prefetch of next h/r after release.
// ---------------------------------------------------------------------------
__global__ void __launch_bounds__(256, 1)
k_recur(const float* __restrict__ Wc, const float* __restrict__ ts,
        const float* __restrict__ init, const float* __restrict__ bc,
        float* __restrict__ out) {
    extern __shared__ float sh[];
    float* Ws  = sh;            // 28672: h-weights  ((g*64+kq)*16 + jw)*4 + e
    float* Wr  = sh + 28672;    //  7168: r-weights  ((g*16+rq)*16 + jw)*4 + e
    float* bs  = sh + 35840;    //   112: bias g*16+j   (+pad to 16B align)
    float* hs  = sh + 35952;    // 2*2048: staged h  float4 idx b*64 + kq
    float* rs  = sh + 40048;    // 2* 512: staged r  float4 idx b*16 + rq
    float* red = sh + 41072;    // 2*4480: partials  (s*7+g)*160 + b*20 + j

    int tid = threadIdx.x;
    int lane = tid & 31;
    int wid = tid >> 5;
    int stream = wid >> 2;           // 0: b 0..7, 1: b 8..15
    int s = wid & 3;                 // k-split 0..3
    int bg = lane >> 4, j1 = lane & 15;
    int bbase = bg * 4;
    int stid = tid & 127;            // stream-local tid
    int j2 = stid & 15, b2 = stid >> 4;

    int group = blockIdx.x >> 4;     // 0..7
    int rank  = blockIdx.x & 15;     // 0..15
    int j0 = rank * 16, jg = j0 + j2;
    int gb0 = group * 16 + stream * 8;
    int gbb = gb0 + b2;              // this thread's output batch
    unsigned* cnt = g_cnt + stream * 8 + group;
    int barid = stream + 1;

    float* hsS  = hs  + stream * 2048;
    float* rsS  = rs  + stream * 512;
    float* redS = red + stream * 4480;

    // one-time weight/bias loads (all 256 threads)
    for (int idx = tid; idx < 28672; idx += 256) {
        int e = idx & 3, jw = (idx >> 2) & 15, kq = (idx >> 6) & 63, g = idx >> 12;
        Ws[idx] = Wc[(size_t)(g * Hq + j0 + jw) * KIN + Eq + kq * 4 + e];
    }
    for (int idx = tid; idx < 7168; idx += 256) {
        int e = idx & 3, jw = (idx >> 2) & 15, rq = (idx >> 6) & 15, g = idx >> 10;
        Wr[idx] = Wc[(size_t)(g * Hq + j0 + jw) * KIN + rq * 4 + e];
    }
    if (tid < 112) bs[tid] = bc[(tid >> 4) * Hq + j0 + (tid & 15)];

    float c_st  = tanhf(init[3 * Hq + jg]);
    float cb_st = tanhf(init[2 * Hq + jg]);
    __syncthreads();   // last full-CTA barrier

    const ulonglong2* WU  = (const ulonglong2*)Ws;
    const ulonglong2* WrU = (const ulonglong2*)Wr;
    const ulonglong2* HU  = (const ulonglong2*)hsS;
    const ulonglong2* RU  = (const ulonglong2*)rsS;
    float4* hs4 = (float4*)hsS;
    float4* rs4 = (float4*)rsS;
    const float4* gr4 = (const float4*)g_r;

    // prefetch registers + prologue (t = 0)
    float4 ph[4], pr;
    float ptc, ptp = 0.f;
    {
        int bb = stid >> 6, kqq = stid & 63;   // bb 0..1
        const float4* gsrc = (const float4*)&g_h[0][0][0];
        #pragma unroll
        for (int i = 0; i < 4; i++)
            ph[i] = __ldcg(gsrc + (gb0 + bb + 2 * i) * 64 + kqq);
        pr  = gr4[((size_t)gbb * Tq + 0) * 16 + j2];
        ptc = ts[gbb * Tq + 0];
    }

    for (int t = 0; t < Tq; t++) {
        // ---- stage from prefetch regs ----
        {
            int bb = stid >> 6, kqq = stid & 63;
            #pragma unroll
            for (int i = 0; i < 4; i++)
                hs4[(bb + 2 * i) * 64 + kqq] = ph[i];
            rs4[stid] = pr;   // idx = b2*16 + j2
        }
        float tc = ptc, tp = ptp;
        asm volatile("bar.sync %0, 128;" :: "r"(barid) : "memory");

        // ---- GEMM: 7 g x 4 b, k-split s (80 k), packed f32x2 ----
        ull acc[7][4];
        #pragma unroll
        for (int g = 0; g < 7; g++)
            #pragma unroll
            for (int bi = 0; bi < 4; bi++) acc[g][bi] = 0ull;

        #pragma unroll
        for (int q = 0; q < 16; q++) {
            int kq = s * 16 + q;
            ulonglong2 hv[4];
            #pragma unroll
            for (int bi = 0; bi < 4; bi++)
                hv[bi] = HU[(bbase + bi) * 64 + kq];
            #pragma unroll
            for (int g = 0; g < 7; g++) {
                ulonglong2 wv = WU[(g * 64 + kq) * 16 + j1];
                #pragma unroll
                for (int bi = 0; bi < 4; bi++) {
                    fma2_(acc[g][bi], wv.x, hv[bi].x);
                    fma2_(acc[g][bi], wv.y, hv[bi].y);
                }
            }
        }
        #pragma unroll
        for (int q2 = 0; q2 < 4; q2++) {
            int rq = s * 4 + q2;
            ulonglong2 rv[4];
            #pragma unroll
            for (int bi = 0; bi < 4; bi++)
                rv[bi] = RU[(bbase + bi) * 16 + rq];
            #pragma unroll
            for (int g = 0; g < 7; g++) {
                ulonglong2 wv = WrU[(g * 16 + rq) * 16 + j1];
                #pragma unroll
                for (int bi = 0; bi < 4; bi++) {
                    fma2_(acc[g][bi], wv.x, rv[bi].x);
                    fma2_(acc[g][bi], wv.y, rv[bi].y);
                }
            }
        }

        // ---- store k-partials (conflict-free) ----
        #pragma unroll
        for (int g = 0; g < 7; g++)
            #pragma unroll
            for (int bi = 0; bi < 4; bi++)
                redS[(s * 7 + g) * 160 + (bbase + bi) * 20 + j1] =
                    lo_(acc[g][bi]) + hi_(acc[g][bi]);
        asm volatile("bar.sync %0, 128;" :: "r"(barid) : "memory");

        // ---- phase 2: reduce 4 partials + gates + decay ----
        float gate[7];
        #pragma unroll
        for (int g = 0; g < 7; g++) {
            float vv = bs[g * 16 + j2];
            #pragma unroll
            for (int sp = 0; sp < 4; sp++)
                vv += redS[(sp * 7 + g) * 160 + b2 * 20 + j2];
            gate[g] = vv;
        }
        float gi  = sigf(gate[0]);
        float gf  = sigf(gate[1]);
        float gz  = tanf_(gate[2]);
        float go  = sigf(gate[3]);
        float gib = sigf(gate[4]);
        float gfb = sigf(gate[5]);
        float gd  = splusf(gate[6]);
        float dt  = tc - tp;

        float ct  = gf * c_st + gi * gz;
        float cbt = gfb * cb_st + gib * gz;
        float cdt = cbt + (ct - cbt) * __expf(-gd * dt);
        float hdt = go * tanf_(cdt);

        c_st = ct; cb_st = cbt;
        __stcg(&g_h[(t & 1) ^ 1][gbb][jg], hdt);

        // ---- release: stream barrier orders all 128 stcg, then publish ----
        asm volatile("bar.sync %0, 128;" :: "r"(barid) : "memory");
        if (stid == 0)
            asm volatile("red.release.gpu.global.add.u32 [%0], %1;"
                         :: "l"(cnt), "r"(1u) : "memory");

        // ---- out writes AFTER release ----
        size_t ob = ((size_t)gbb * (Tq + 1) + t + 1) * (size_t)(6 * Hq) + jg;
        __stcs(&out[ob + 0 * Hq], hdt);
        __stcs(&out[ob + 1 * Hq], go);
        __stcs(&out[ob + 2 * Hq], cbt);
        __stcs(&out[ob + 3 * Hq], ct);
        __stcs(&out[ob + 4 * Hq], gd);
        __stcs(&out[ob + 5 * Hq], cdt);

        // ---- prefetch next step's h/r (poll + ldcg) ----
        if (t < Tq - 1) {
            unsigned target = 16u * (unsigned)(t + 1), v;
            do {
                asm volatile("ld.acquire.gpu.u32 %0, [%1];"
                             : "=r"(v) : "l"(cnt) : "memory");
            } while (v < target);

            int bb = stid >> 6, kqq = stid & 63;
            const float4* gsrc = (const float4*)&g_h[(t + 1) & 1][0][0];
            #pragma unroll
            for (int i = 0; i < 4; i++)
                ph[i] = __ldcg(gsrc + (gb0 + bb + 2 * i) * 64 + kqq);
            pr  = gr4[((size_t)gbb * Tq + t + 1) * 16 + j2];
            ptp = tc;
            ptc = ts[gbb * Tq + t + 1];
        }
    }
}

// ---------------------------------------------------------------------------
extern "C" void kernel_launch(void* const* d_in, const int* in_sizes, int n_in,
                              void* d_out, int out_size) {
    const float* marks = (const float*)d_in[0];
    const float* ts    = (const float*)d_in[1];
    const float* Wemb  = (const float*)d_in[2];
    const float* Wc    = (const float*)d_in[3];
    const float* bc    = (const float*)d_in[4];
    const float* init  = (const float*)d_in[5];
    float* out = (float*)d_out;

    k_embed<<<Bq * Tq, 128>>>(marks, Wemb);
    k_init<<<Bq, 256>>>(init, out);

    const int SMEM = 50032 * (int)sizeof(float);   // 200,128 B
    cudaFuncSetAttribute(k_recur, cudaFuncAttributeMaxDynamicSharedMemorySize, SMEM);
    k_recur<<<128, 256, SMEM>>>(Wc, ts, init, bc, out);
}